// round 2
// baseline (speedup 1.0000x reference)
#include <cuda_runtime.h>
#include <cuda_bf16.h>
#include <cstdint>

// WeightOnlyInt8Linear: out[M,N] = x[M,K] @ W[N,K]^T * scales[N] + bias[N]
// M = B*S = 2048, K = 4096, N = 4096.
//
// Round 1: weight buffer is int32 (harness widens int8 -> int32; round-0
// rel_err 1.1175 == sqrt(1.25), the exact signature of reading int32 as int8).
// fp32 SIMT tiled GEMM: 128x128x16 block tile, 256 threads, 8x8 per thread.

#define BM 128
#define BN 128
#define BK 16
#define TM 8
#define TN 8
#define NTHREADS 256

__global__ __launch_bounds__(NTHREADS, 2)
void wint8_gemm_kernel(const float* __restrict__ x,
                       const int* __restrict__ w,      // int32 weights in [-128,127]
                       const float* __restrict__ scales,
                       const float* __restrict__ bias,
                       float* __restrict__ out,
                       int M, int N, int K) {
    __shared__ float As[BK][BM];   // x tile, transposed: [k][m]
    __shared__ float Bs[BK][BN];   // w tile, transposed: [k][n] (dequantized, unscaled)

    const int bx = blockIdx.x;     // N tile index
    const int by = blockIdx.y;     // M tile index
    const int tid = threadIdx.x;
    const int tx = tid & 15;       // 0..15  (N direction)
    const int ty = tid >> 4;       // 0..15  (M direction)

    const float* xtile = x + (size_t)(by * BM) * K;
    const int*   wtile = w + (size_t)(bx * BN) * K;

    float acc[TM][TN];
    #pragma unroll
    for (int i = 0; i < TM; i++)
        #pragma unroll
        for (int j = 0; j < TN; j++)
            acc[i][j] = 0.0f;

    // A: 128 rows x 16 k = 512 float4; 256 threads -> 2 float4 each.
    // B: 128 rows x 16 k int32 = 512 int4-pairs; row = tid/2, k0 = (tid%2)*8, 2x int4 each.
    const int a_row0 = (tid + 0 * NTHREADS) >> 2;
    const int a_k0_0 = ((tid + 0 * NTHREADS) & 3) << 2;
    const int a_row1 = (tid + 1 * NTHREADS) >> 2;
    const int a_k0_1 = ((tid + 1 * NTHREADS) & 3) << 2;
    const int b_row = tid >> 1;
    const int b_k0  = (tid & 1) << 3;

    for (int kk = 0; kk < K; kk += BK) {
        // --- load A tile (transposed into smem) ---
        {
            float4 v0 = *reinterpret_cast<const float4*>(&xtile[(size_t)a_row0 * K + kk + a_k0_0]);
            As[a_k0_0 + 0][a_row0] = v0.x;
            As[a_k0_0 + 1][a_row0] = v0.y;
            As[a_k0_0 + 2][a_row0] = v0.z;
            As[a_k0_0 + 3][a_row0] = v0.w;
            float4 v1 = *reinterpret_cast<const float4*>(&xtile[(size_t)a_row1 * K + kk + a_k0_1]);
            As[a_k0_1 + 0][a_row1] = v1.x;
            As[a_k0_1 + 1][a_row1] = v1.y;
            As[a_k0_1 + 2][a_row1] = v1.z;
            As[a_k0_1 + 3][a_row1] = v1.w;
        }
        // --- load + dequant B tile (int32 -> f32, transposed into smem) ---
        {
            const int4* p = reinterpret_cast<const int4*>(&wtile[(size_t)b_row * K + kk + b_k0]);
            int4 q0 = p[0];
            int4 q1 = p[1];
            Bs[b_k0 + 0][b_row] = __int2float_rn(q0.x);
            Bs[b_k0 + 1][b_row] = __int2float_rn(q0.y);
            Bs[b_k0 + 2][b_row] = __int2float_rn(q0.z);
            Bs[b_k0 + 3][b_row] = __int2float_rn(q0.w);
            Bs[b_k0 + 4][b_row] = __int2float_rn(q1.x);
            Bs[b_k0 + 5][b_row] = __int2float_rn(q1.y);
            Bs[b_k0 + 6][b_row] = __int2float_rn(q1.z);
            Bs[b_k0 + 7][b_row] = __int2float_rn(q1.w);
        }
        __syncthreads();

        // --- compute ---
        #pragma unroll
        for (int k = 0; k < BK; k++) {
            float4 a0 = *reinterpret_cast<const float4*>(&As[k][ty * TM + 0]);
            float4 a1 = *reinterpret_cast<const float4*>(&As[k][ty * TM + 4]);
            float4 b0 = *reinterpret_cast<const float4*>(&Bs[k][tx * TN + 0]);
            float4 b1 = *reinterpret_cast<const float4*>(&Bs[k][tx * TN + 4]);
            float a[TM] = {a0.x, a0.y, a0.z, a0.w, a1.x, a1.y, a1.z, a1.w};
            float b[TN] = {b0.x, b0.y, b0.z, b0.w, b1.x, b1.y, b1.z, b1.w};
            #pragma unroll
            for (int i = 0; i < TM; i++)
                #pragma unroll
                for (int j = 0; j < TN; j++)
                    acc[i][j] = fmaf(a[i], b[j], acc[i][j]);
        }
        __syncthreads();
    }

    // --- epilogue: per-channel scale + bias, vectorized stores ---
    const int n_base = bx * BN + tx * TN;
    float4 s0 = *reinterpret_cast<const float4*>(&scales[n_base + 0]);
    float4 s1 = *reinterpret_cast<const float4*>(&scales[n_base + 4]);
    float4 g0 = *reinterpret_cast<const float4*>(&bias[n_base + 0]);
    float4 g1 = *reinterpret_cast<const float4*>(&bias[n_base + 4]);
    float s[TN] = {s0.x, s0.y, s0.z, s0.w, s1.x, s1.y, s1.z, s1.w};
    float g[TN] = {g0.x, g0.y, g0.z, g0.w, g1.x, g1.y, g1.z, g1.w};

    #pragma unroll
    for (int i = 0; i < TM; i++) {
        const int m = by * BM + ty * TM + i;
        float4 o0, o1;
        o0.x = fmaf(acc[i][0], s[0], g[0]);
        o0.y = fmaf(acc[i][1], s[1], g[1]);
        o0.z = fmaf(acc[i][2], s[2], g[2]);
        o0.w = fmaf(acc[i][3], s[3], g[3]);
        o1.x = fmaf(acc[i][4], s[4], g[4]);
        o1.y = fmaf(acc[i][5], s[5], g[5]);
        o1.z = fmaf(acc[i][6], s[6], g[6]);
        o1.w = fmaf(acc[i][7], s[7], g[7]);
        *reinterpret_cast<float4*>(&out[(size_t)m * N + n_base + 0]) = o0;
        *reinterpret_cast<float4*>(&out[(size_t)m * N + n_base + 4]) = o1;
    }
}

extern "C" void kernel_launch(void* const* d_in, const int* in_sizes, int n_in,
                              void* d_out, int out_size) {
    const float* x      = (const float*)d_in[0];
    const int*   weight = (const int*)d_in[1];     // int32 (harness-widened int8)
    const float* scales = (const float*)d_in[2];
    const float* bias   = (const float*)d_in[3];
    float*       out    = (float*)d_out;

    const int N = in_sizes[2];            // 4096
    const int K = in_sizes[1] / N;        // 4096
    const int M = in_sizes[0] / K;        // 2048

    dim3 grid(N / BN, M / BM);
    dim3 block(NTHREADS);
    wint8_gemm_kernel<<<grid, block>>>(x, weight, scales, bias, out, M, N, K);
}

// round 4
// speedup vs baseline: 5.8015x; 5.8015x over previous
#include <cuda_runtime.h>
#include <cuda_bf16.h>
#include <cstdint>

// WeightOnlyInt8Linear on GB300, tf32 mma.sync path (tcgen05 unavailable:
// harness PTX target is compute_103, no '-a' features).
// out[M,N] = x[M,K] @ W[N,K]^T * scales[N] + bias[N],  M=2048, N=4096, K=4096.
//
// W int32 -> float (exact, in-kernel I2F). x fp32 -> tf32 via cvt.rna (rel err ~2e-4).
// CTA tile 128x128x32, 8 warps (2x4), warp tile 64x32, 3-stage cp.async pipeline.

#define BM 128
#define BN 128
#define BK 32
#define NSTAGES 3
#define NTHREADS 256

// smem: padded row stride 36 floats (144B) -> conflict-free fragment loads
#define ROW_B   144
#define A_BYTES (128 * ROW_B)            // 18432
#define STAGE_B (2 * A_BYTES)            // 36864 (A then B)
#define SMEM_TOTAL (NSTAGES * STAGE_B)   // 110592

__device__ __forceinline__ uint32_t smem_u32(const void* p) {
    uint32_t a;
    asm("{ .reg .u64 t; cvta.to.shared.u64 t, %1; cvt.u32.u64 %0, t; }" : "=r"(a) : "l"(p));
    return a;
}
__device__ __forceinline__ void cp_async16(uint32_t dst, const void* src) {
    asm volatile("cp.async.cg.shared.global [%0], [%1], 16;" :: "r"(dst), "l"(src));
}
__device__ __forceinline__ void cp_commit() {
    asm volatile("cp.async.commit_group;" ::: "memory");
}
template <int N_>
__device__ __forceinline__ void cp_wait() {
    asm volatile("cp.async.wait_group %0;" :: "n"(N_) : "memory");
}
__device__ __forceinline__ uint32_t f32_to_tf32(float f) {
    uint32_t r;
    asm("cvt.rna.tf32.f32 %0, %1;" : "=r"(r) : "f"(f));
    return r;
}
__device__ __forceinline__ void mma_tf32(float* d, const uint32_t* a, const uint32_t* b) {
    asm volatile(
        "mma.sync.aligned.m16n8k8.row.col.f32.tf32.tf32.f32 "
        "{%0,%1,%2,%3}, {%4,%5,%6,%7}, {%8,%9}, {%0,%1,%2,%3};"
        : "+f"(d[0]), "+f"(d[1]), "+f"(d[2]), "+f"(d[3])
        : "r"(a[0]), "r"(a[1]), "r"(a[2]), "r"(a[3]), "r"(b[0]), "r"(b[1]));
}

__global__ __launch_bounds__(NTHREADS, 2)
void wint8_mma_kernel(const float* __restrict__ x,
                      const int* __restrict__ w,       // int32 weights in [-128,127]
                      const float* __restrict__ scales,
                      const float* __restrict__ bias,
                      float* __restrict__ out,
                      int M, int N, int K) {
    extern __shared__ __align__(128) char smem[];
    const uint32_t sb = smem_u32(smem);

    const int tid  = threadIdx.x;
    const int lane = tid & 31;
    const int wid  = tid >> 5;
    const int wm   = (wid >> 2) * 64;     // warp M offset within CTA tile
    const int wn   = (wid & 3) * 32;      // warp N offset within CTA tile

    const int m0 = blockIdx.y * BM;
    const int n0 = blockIdx.x * BN;

    // cp.async mapping: 256 threads, each loads 16B per row-pass.
    const int ld_row = tid >> 3;          // 0..31
    const int ld_cg  = tid & 7;           // 0..7 (16B chunks of a 128B row)

    const float* xbase = x + (size_t)(m0)*K;
    const int*   wbase = w + (size_t)(n0)*K;

    auto load_stage = [&](int s, int kk) {
        const uint32_t abase = sb + s * STAGE_B;
        const uint32_t bbase = abase + A_BYTES;
        #pragma unroll
        for (int p = 0; p < 4; p++) {
            const int r = p * 32 + ld_row;
            cp_async16(abase + r * ROW_B + ld_cg * 16,
                       xbase + (size_t)r * K + kk + ld_cg * 4);
            cp_async16(bbase + r * ROW_B + ld_cg * 16,
                       wbase + (size_t)r * K + kk + ld_cg * 4);
        }
    };

    const int NIT = K / BK;   // 128

    // prologue: fill NSTAGES-1 stages
    load_stage(0, 0);
    cp_commit();
    load_stage(1, BK);
    cp_commit();

    float acc[4][4][4];
    #pragma unroll
    for (int mi = 0; mi < 4; mi++)
        #pragma unroll
        for (int ni = 0; ni < 4; ni++)
            #pragma unroll
            for (int c = 0; c < 4; c++)
                acc[mi][ni][c] = 0.0f;

    const int fr = lane >> 2;   // 0..7  (row within fragment)
    const int fc = lane & 3;    // 0..3  (col within fragment)

    for (int it = 0; it < NIT; ++it) {
        cp_wait<NSTAGES - 2>();
        __syncthreads();

        const char* As = smem + (it % NSTAGES) * STAGE_B;
        const char* Bs = As + A_BYTES;

        #pragma unroll
        for (int ks = 0; ks < 4; ks++) {
            const int kc = ks * 8 + fc;
            uint32_t afrag[4][4];
            #pragma unroll
            for (int mi = 0; mi < 4; mi++) {
                const int r = wm + mi * 16 + fr;
                const float* pa = reinterpret_cast<const float*>(As + r * ROW_B + kc * 4);
                // a0:(r,c) a1:(r+8,c) a2:(r,c+4) a3:(r+8,c+4); row stride ROW_B, +8 rows = 8*ROW_B
                afrag[mi][0] = f32_to_tf32(pa[0]);
                afrag[mi][1] = f32_to_tf32(*reinterpret_cast<const float*>(As + (r + 8) * ROW_B + kc * 4));
                afrag[mi][2] = f32_to_tf32(pa[4]);
                afrag[mi][3] = f32_to_tf32(*reinterpret_cast<const float*>(As + (r + 8) * ROW_B + (kc + 4) * 4));
            }
            uint32_t bfrag[4][2];
            #pragma unroll
            for (int ni = 0; ni < 4; ni++) {
                const int r = wn + ni * 8 + fr;   // n index
                const int* pb = reinterpret_cast<const int*>(Bs + r * ROW_B + kc * 4);
                bfrag[ni][0] = __float_as_uint((float)pb[0]);   // exact I2F, valid tf32
                bfrag[ni][1] = __float_as_uint((float)pb[4]);
            }
            #pragma unroll
            for (int mi = 0; mi < 4; mi++)
                #pragma unroll
                for (int ni = 0; ni < 4; ni++)
                    mma_tf32(acc[mi][ni], afrag[mi], bfrag[ni]);
        }

        __syncthreads();
        const int nxt = it + NSTAGES - 1;
        if (nxt < NIT) load_stage(nxt % NSTAGES, nxt * BK);
        cp_commit();
    }

    // ---- epilogue: scale + bias, float2 stores ----
    #pragma unroll
    for (int ni = 0; ni < 4; ni++) {
        const int col = n0 + wn + ni * 8 + fc * 2;
        const float s0 = __ldg(&scales[col]);
        const float s1 = __ldg(&scales[col + 1]);
        const float g0 = __ldg(&bias[col]);
        const float g1 = __ldg(&bias[col + 1]);
        #pragma unroll
        for (int mi = 0; mi < 4; mi++) {
            const int row = m0 + wm + mi * 16 + fr;
            float2 o0, o1;
            o0.x = fmaf(acc[mi][ni][0], s0, g0);
            o0.y = fmaf(acc[mi][ni][1], s1, g1);
            o1.x = fmaf(acc[mi][ni][2], s0, g0);
            o1.y = fmaf(acc[mi][ni][3], s1, g1);
            *reinterpret_cast<float2*>(out + (size_t)row * N + col) = o0;
            *reinterpret_cast<float2*>(out + (size_t)(row + 8) * N + col) = o1;
        }
    }
}

extern "C" void kernel_launch(void* const* d_in, const int* in_sizes, int n_in,
                              void* d_out, int out_size) {
    const float* x      = (const float*)d_in[0];
    const int*   weight = (const int*)d_in[1];     // int32 (harness-widened int8)
    const float* scales = (const float*)d_in[2];
    const float* bias   = (const float*)d_in[3];
    float*       out    = (float*)d_out;

    const int N = in_sizes[2];            // 4096
    const int K = in_sizes[1] / N;        // 4096
    const int M = in_sizes[0] / K;        // 2048

    cudaFuncSetAttribute(wint8_mma_kernel,
                         cudaFuncAttributeMaxDynamicSharedMemorySize, SMEM_TOTAL);

    dim3 grid(N / BN, M / BM);   // (32, 16)
    wint8_mma_kernel<<<grid, NTHREADS, SMEM_TOTAL>>>(x, weight, scales, bias, out, M, N, K);
}